// round 1
// baseline (speedup 1.0000x reference)
#include <cuda_runtime.h>
#include <math.h>

// Triplet-margin ranking loss, GB300 sm_103a.
// anchor: (1, 2400) f32, positive: (P=5, 2400) f32, negative: (N=100000, 2400) f32
// loss = sum_{i<num_full} relu(d_ap[i % P] - d_an[i] + MARGIN)
// d_x = || anchor - x + EPS ||_2  (elementwise +EPS, torch pairwise_distance)

#define EPS    1e-6f
#define MARGIN 1.0f
#define DIM    2400
#define DIM4   (DIM / 4)   // 600 float4 per row

// d_ap values (P <= 8 supported; problem has P = 5)
__device__ float g_dap[8];

// ---------------------------------------------------------------------------
// Kernel 1: compute d_ap[j] for each positive row; also zero the output scalar
// (d_out is poisoned to 0xAA by the harness).
// One block, warp j handles positive row j.
// ---------------------------------------------------------------------------
__global__ void dap_kernel(const float* __restrict__ anchor,
                           const float* __restrict__ pos,
                           float* __restrict__ out,
                           int P)
{
    const int wid  = threadIdx.x >> 5;
    const int lane = threadIdx.x & 31;

    if (threadIdx.x == 0) out[0] = 0.0f;

    if (wid < P) {
        const float4* a4 = reinterpret_cast<const float4*>(anchor);
        const float4* p4 = reinterpret_cast<const float4*>(pos + (size_t)wid * DIM);
        float s = 0.0f;
        for (int k = lane; k < DIM4; k += 32) {
            float4 a = a4[k];
            float4 p = p4[k];
            float d0 = a.x - p.x + EPS;
            float d1 = a.y - p.y + EPS;
            float d2 = a.z - p.z + EPS;
            float d3 = a.w - p.w + EPS;
            s = fmaf(d0, d0, s);
            s = fmaf(d1, d1, s);
            s = fmaf(d2, d2, s);
            s = fmaf(d3, d3, s);
        }
        #pragma unroll
        for (int o = 16; o > 0; o >>= 1)
            s += __shfl_xor_sync(0xFFFFFFFFu, s, o);
        if (lane == 0) g_dap[wid] = sqrtf(s);
    }
}

// ---------------------------------------------------------------------------
// Kernel 2: streaming over negative rows. Warp-per-row, grid-stride.
// Anchor staged in shared (9.6 KB). One atomicAdd per block.
// ---------------------------------------------------------------------------
__global__ void __launch_bounds__(256, 8)
loss_kernel(const float* __restrict__ anchor,
            const float* __restrict__ neg,
            float* __restrict__ out,
            int num_full, int P)
{
    __shared__ float4 sA[DIM4];        // anchor, 9600 B
    __shared__ float  sDap[8];
    __shared__ float  sWarp[8];

    // stage anchor into shared
    const float4* a4 = reinterpret_cast<const float4*>(anchor);
    for (int k = threadIdx.x; k < DIM4; k += blockDim.x)
        sA[k] = a4[k];
    if (threadIdx.x < 8)
        sDap[threadIdx.x] = (threadIdx.x < P) ? g_dap[threadIdx.x] : 0.0f;
    __syncthreads();

    const int wid    = threadIdx.x >> 5;
    const int lane   = threadIdx.x & 31;
    const int nwarps = blockDim.x >> 5;
    const int gwarp  = blockIdx.x * nwarps + wid;
    const int W      = gridDim.x * nwarps;

    float acc = 0.0f;

    for (int row = gwarp; row < num_full; row += W) {
        const float4* n4 = reinterpret_cast<const float4*>(neg + (size_t)row * DIM);
        float s = 0.0f;
        // 600 float4 / 32 lanes = 18.75 iterations; unroll for MLP
        #pragma unroll 4
        for (int k = lane; k < DIM4; k += 32) {
            float4 a = sA[k];
            float4 n = __ldg(&n4[k]);
            float d0 = a.x - n.x + EPS;
            float d1 = a.y - n.y + EPS;
            float d2 = a.z - n.z + EPS;
            float d3 = a.w - n.w + EPS;
            s = fmaf(d0, d0, s);
            s = fmaf(d1, d1, s);
            s = fmaf(d2, d2, s);
            s = fmaf(d3, d3, s);
        }
        #pragma unroll
        for (int o = 16; o > 0; o >>= 1)
            s += __shfl_xor_sync(0xFFFFFFFFu, s, o);
        if (lane == 0) {
            float d_an = sqrtf(s);
            float t = sDap[row % P] - d_an + MARGIN;
            acc += (t > 0.0f) ? t : 0.0f;
        }
    }

    // block reduction: lane 0 of each warp holds its partial
    if (lane == 0) sWarp[wid] = acc;
    __syncthreads();
    if (threadIdx.x == 0) {
        float b = 0.0f;
        for (int i = 0; i < nwarps; i++) b += sWarp[i];
        atomicAdd(out, b);
    }
}

// ---------------------------------------------------------------------------
extern "C" void kernel_launch(void* const* d_in, const int* in_sizes, int n_in,
                              void* d_out, int out_size)
{
    const float* anchor = (const float*)d_in[0];
    const float* pos    = (const float*)d_in[1];
    const float* neg    = (const float*)d_in[2];
    float* out = (float*)d_out;

    const int P = in_sizes[1] / DIM;          // 5
    const int N = in_sizes[2] / DIM;          // 100000
    const int num_full = (N / P) * P;         // 100000

    dap_kernel<<<1, 256>>>(anchor, pos, out, P);

    // 148 SMs x 8 blocks of 256 threads = full occupancy
    const int grid = 148 * 8;
    loss_kernel<<<grid, 256>>>(anchor, neg, out, num_full, P);
}